// round 2
// baseline (speedup 1.0000x reference)
#include <cuda_runtime.h>
#include <cstdint>

#define PI_F 3.14159265358979323846f          /* rounds to 3.1415927f, matches f32(np.pi) */
#define ANG_THR 0.08726646259971647f          /* radians(5.0) = pi/36 */
#define EMAX 8192
#define PMAX ((EMAX*(EMAX-1))/2)              /* worst-case pairs */
#define NB 35                                 /* bucket width pi/35 > thr (2.9% margin) */

// -------------------- device scratch (static: no allocation allowed) --------
__device__ float g_ang[EMAX], g_nx[EMAX], g_ny[EMAX], g_off[EMAX], g_mx[EMAX], g_my[EMAX];
__device__ int   g_bkt[EMAX];
__device__ float g_sang[EMAX];                 // bucket-sorted angles
__device__ int   g_sorig[EMAX];                // bucket-sorted original indices
__device__ int   g_boff[NB + 1];               // bucket offsets
__device__ unsigned g_cnt[EMAX];               // per-sorted-pos candidate counts
__device__ unsigned g_offs[EMAX];              // exclusive offsets
__device__ unsigned g_count;                   // n_pairs
__device__ float    g_vals[PMAX];              // masked distances (computed ONCE)
__device__ unsigned g_pair[PMAX];              // flat index i*E+j  (< 2^26)
__device__ unsigned g_hist[3][256];
__device__ unsigned g_pref[3];
__device__ unsigned g_rank[3];
__device__ float g_mu, g_margin;
__device__ float g_partial[2048];

__device__ __forceinline__ bool pair_ok(float ai, float aj) {
    float df = fabsf(aj - ai);
    df = fminf(df, PI_F - df);
    return df < ANG_THR;
}
__device__ __forceinline__ float pair_dist(float nx, float ny, float off, float mx, float my) {
    return fabsf(nx * mx + ny * my - off);
}

// -------------------- K1: per-edge geometry + bucket ------------------------
__global__ void k_edges(const float* __restrict__ pos, const int* __restrict__ eidx, int E) {
    int idx = blockIdx.x * blockDim.x + threadIdx.x;
    if (idx >= E) return;
    int s = eidx[idx];
    int d = eidx[E + idx];
    float sx = pos[2 * s], sy = pos[2 * s + 1];
    float dx = pos[2 * d], dy = pos[2 * d + 1];
    float ddx = dx - sx, ddy = dy - sy;
    float len = fmaxf(sqrtf(ddx * ddx + ddy * ddy), 1e-8f);
    float ux = ddx / len, uy = ddy / len;
    float a = atan2f(uy, ux);
    a = fmodf(a, PI_F);
    if (a < 0.f) a += PI_F;
    g_ang[idx] = a;
    g_nx[idx] = -uy;
    g_ny[idx] = ux;
    g_off[idx] = sx * (-uy) + sy * ux;
    g_mx[idx] = (sx + dx) * 0.5f;
    g_my[idx] = (sy + dy) * 0.5f;
    int b = (int)(a * (11.140846016432674f));  // a * 35/pi
    b = (b < 0) ? 0 : ((b >= NB) ? NB - 1 : b);
    g_bkt[idx] = b;
}

// -------------------- K2: stable counting sort by bucket (1 block) ----------
__global__ void k_bsort(int E) {
    __shared__ unsigned s_cnt[NB * 256];       // (bin-major, thread-minor)
    __shared__ unsigned s_ws[256];
    int t = threadIdx.x;                        // 256 threads, 32 elems each
    for (int b = 0; b < NB; b++) s_cnt[b * 256 + t] = 0;
    __syncthreads();
    int base = t * 32;
    for (int k = 0; k < 32; k++) s_cnt[g_bkt[base + k] * 256 + t]++;
    __syncthreads();
    // exclusive scan over flattened 35*256 = 8960 entries: chunks of 35/thread
    unsigned s = 0;
    for (int k = 0; k < 35; k++) s += s_cnt[t * 35 + k];
    s_ws[t] = s;
    __syncthreads();
    if (t == 0) {                               // 256-entry scan, trivial
        unsigned acc = 0;
        for (int k = 0; k < 256; k++) { unsigned v = s_ws[k]; s_ws[k] = acc; acc += v; }
    }
    __syncthreads();
    unsigned acc = s_ws[t];
    for (int k = 0; k < 35; k++) { unsigned v = s_cnt[t * 35 + k]; s_cnt[t * 35 + k] = acc; acc += v; }
    __syncthreads();
    if (t < NB) g_boff[t] = (int)s_cnt[t * 256];
    if (t == 0) g_boff[NB] = E;
    // stable scatter
    for (int k = 0; k < 32; k++) {
        int e = base + k;
        int b = g_bkt[e];
        unsigned p = s_cnt[b * 256 + t]++;
        g_sang[p] = g_ang[e];
        g_sorig[p] = e;
    }
}

// -------------------- K3: count candidates per sorted position --------------
__global__ void k_count(int E) {
    int gid = blockIdx.x * blockDim.x + threadIdx.x;
    int p = gid >> 5;
    int lane = gid & 31;
    if (p >= E) return;
    float ap = g_sang[p];
    int b = g_bkt[g_sorig[p]];
    int end1 = g_boff[b + 1];
    int bn = (b + 1 == NB) ? 0 : (b + 1);
    int lo2 = g_boff[bn], hi2 = g_boff[bn + 1];
    unsigned c = 0;
    for (int q = p + 1 + lane; q < end1; q += 32) c += pair_ok(ap, g_sang[q]) ? 1u : 0u;
    for (int q = lo2 + lane;   q < hi2;  q += 32) c += pair_ok(ap, g_sang[q]) ? 1u : 0u;
    for (int o = 16; o; o >>= 1) c += __shfl_down_sync(0xffffffffu, c, o);
    if (lane == 0) g_cnt[p] = c;
}

// -------------------- K4: exclusive prefix scan (8192, one block) -----------
__global__ void k_scan(int E) {
    __shared__ unsigned s_ws[32];
    int t = threadIdx.x;                        // 1024 threads x 8 elems
    unsigned loc[8]; unsigned s = 0;
#pragma unroll
    for (int k = 0; k < 8; k++) { loc[k] = g_cnt[t * 8 + k]; s += loc[k]; }
    unsigned v = s;
    for (int o = 1; o < 32; o <<= 1) { unsigned u = __shfl_up_sync(0xffffffffu, v, o); if ((t & 31) >= o) v += u; }
    if ((t & 31) == 31) s_ws[t >> 5] = v;
    __syncthreads();
    if (t < 32) {
        unsigned w = s_ws[t];
        for (int o = 1; o < 32; o <<= 1) { unsigned u = __shfl_up_sync(0xffffffffu, w, o); if (t >= o) w += u; }
        s_ws[t] = w;                            // inclusive warp sums
    }
    __syncthreads();
    unsigned excl = v - s + ((t >= 32) ? s_ws[(t >> 5) - 1] : 0u);
    unsigned acc = excl;
#pragma unroll
    for (int k = 0; k < 8; k++) { g_offs[t * 8 + k] = acc; acc += loc[k]; }
    if (t == 1023) g_count = acc;
}

// -------------------- K5: emit (dist, flat idx) at exact offsets -------------
__global__ void k_emit(int E) {
    int gid = blockIdx.x * blockDim.x + threadIdx.x;
    int p = gid >> 5;
    int lane = gid & 31;
    if (p >= E) return;
    float ap = g_sang[p];
    int op = g_sorig[p];
    int b = g_bkt[op];
    int end1 = g_boff[b + 1];
    int bn = (b + 1 == NB) ? 0 : (b + 1);
    int lo2 = g_boff[bn], hi2 = g_boff[bn + 1];
    unsigned base = g_offs[p];
    unsigned lm = (1u << lane) - 1u;

#pragma unroll 1
    for (int q0 = p + 1; q0 < end1; q0 += 32) {
        int q = q0 + lane;
        bool ok = (q < end1) && pair_ok(ap, g_sang[q]);
        unsigned bal = __ballot_sync(0xffffffffu, ok);
        if (ok) {
            unsigned posn = base + __popc(bal & lm);
            int oq = g_sorig[q];
            int i = min(op, oq), j = max(op, oq);
            g_vals[posn] = pair_dist(g_nx[i], g_ny[i], g_off[i], g_mx[j], g_my[j]);
            g_pair[posn] = (unsigned)i * (unsigned)E + (unsigned)j;
        }
        base += __popc(bal);
    }
#pragma unroll 1
    for (int q0 = lo2; q0 < hi2; q0 += 32) {
        int q = q0 + lane;
        bool ok = (q < hi2) && pair_ok(ap, g_sang[q]);
        unsigned bal = __ballot_sync(0xffffffffu, ok);
        if (ok) {
            unsigned posn = base + __popc(bal & lm);
            int oq = g_sorig[q];
            int i = min(op, oq), j = max(op, oq);
            g_vals[posn] = pair_dist(g_nx[i], g_ny[i], g_off[i], g_mx[j], g_my[j]);
            g_pair[posn] = (unsigned)i * (unsigned)E + (unsigned)j;
        }
        base += __popc(bal);
    }
}

// -------------------- K6: init ranks + zero histograms -----------------------
__global__ void k_ranks() {
    int tid = threadIdx.x;                      // 256 threads
    unsigned* h = (unsigned*)g_hist;
    for (int t = tid; t < 768; t += 256) h[t] = 0;
    if (tid == 0) {
        unsigned n = g_count;
        unsigned k1 = 0, kmu = 0, k3 = 0;
        if (n > 0) {
            unsigned q = n / 4u;
            k1 = (q >= 1u) ? q - 1u : 0u;
            kmu = n / 2u;
            unsigned a = (3u * n) / 4u;
            k3 = (a < n - 1u) ? a : (n - 1u);
        }
        g_rank[0] = k1; g_rank[1] = kmu; g_rank[2] = k3;
        g_pref[0] = 0;  g_pref[1] = 0;   g_pref[2] = 0;
    }
}

// -------------------- K7: radix-select histogram pass ------------------------
__global__ void k_hist(int p) {
    __shared__ unsigned sh[768];
    int tid = threadIdx.x;
    for (int t = tid; t < 768; t += blockDim.x) sh[t] = 0;
    __syncthreads();
    unsigned n = g_count;
    int shift = 24 - 8 * p;
    unsigned p0 = g_pref[0], p1 = g_pref[1], p2 = g_pref[2];
    unsigned long long hs = (unsigned long long)(shift + 8);
    for (unsigned idx = blockIdx.x * blockDim.x + tid; idx < n; idx += gridDim.x * blockDim.x) {
        unsigned u = __float_as_uint(g_vals[idx]);
        unsigned dig = (u >> shift) & 255u;
        bool m0, m1, m2;
        if (p == 0) { m0 = m1 = m2 = true; }
        else {
            m0 = (((unsigned long long)(u ^ p0)) >> hs) == 0ull;
            m1 = (((unsigned long long)(u ^ p1)) >> hs) == 0ull;
            m2 = (((unsigned long long)(u ^ p2)) >> hs) == 0ull;
        }
        if (m0) atomicAdd(&sh[dig], 1u);
        if (m1) atomicAdd(&sh[256 + dig], 1u);
        if (m2) atomicAdd(&sh[512 + dig], 1u);
    }
    __syncthreads();
    unsigned* h = (unsigned*)g_hist;
    for (int t = tid; t < 768; t += blockDim.x) {
        unsigned v = sh[t];
        if (v) atomicAdd(&h[t], v);
    }
}

// -------------------- K8: resolve one radix digit -----------------------------
__global__ void k_resolve(int p) {
    __shared__ unsigned s_h[3][256];
    int tid = threadIdx.x;                      // 256
    for (int t = 0; t < 3; t++) s_h[t][tid] = g_hist[t][tid];
    __syncthreads();
    if (tid < 3) {
        int t = tid;
        unsigned rank = g_rank[t];
        unsigned cum = 0;
        int shift = 24 - 8 * p;
        unsigned sel = 255u;
        for (int b = 0; b < 256; b++) {
            unsigned c = s_h[t][b];
            if (cum + c > rank) { sel = (unsigned)b; break; }
            cum += c;
        }
        g_pref[t] |= sel << shift;
        g_rank[t] = rank - cum;
    }
    __syncthreads();
    for (int t = 0; t < 3; t++) g_hist[t][tid] = 0;
    if (p == 3 && tid == 0) {
        unsigned n = g_count;
        if (n == 0) { g_mu = 0.f; g_margin = 0.f; }
        else {
            float q1 = __uint_as_float(g_pref[0]);
            float mu = __uint_as_float(g_pref[1]);
            float q3 = __uint_as_float(g_pref[2]);
            g_mu = mu;
            g_margin = fmaxf(q3 - q1, 1e-6f) * 0.75f;
        }
    }
}

// -------------------- K9: scatter masked entries into zeroed planes ----------
__global__ void k_scatter(float* __restrict__ dout, int E) {
    __shared__ float s_red[256];
    int tid = threadIdx.x;
    unsigned n = g_count;
    float mu = g_mu, mg = g_margin;
    size_t EE = (size_t)E * (size_t)E;
    float* omask = dout + 1;
    float* oloss = dout + 1 + EE;
    float lsum = 0.f;
    for (unsigned idx = blockIdx.x * 256u + tid; idx < n; idx += gridDim.x * 256u) {
        float d = g_vals[idx];
        unsigned pr = g_pair[idx];
        float l = fmaxf(fabsf(d - mu) - mg, 0.f);
        omask[pr] = (l > 0.f) ? 1.f : 0.f;
        oloss[pr] = l;
        lsum += l;
    }
    s_red[tid] = lsum;
    __syncthreads();
    for (int o = 128; o > 0; o >>= 1) {
        if (tid < o) s_red[tid] += s_red[tid + o];
        __syncthreads();
    }
    if (tid == 0) g_partial[blockIdx.x] = s_red[0];
}

// -------------------- K10: final deterministic reduction + scalars -----------
__global__ void k_reduce(float* __restrict__ dout, const float* __restrict__ weight,
                         long long out_size, int npart) {
    __shared__ float s[1024];
    int tid = threadIdx.x;
    float v = 0.f;
    for (int t = tid; t < npart; t += 1024) v += g_partial[t];
    s[tid] = v;
    __syncthreads();
    for (int o = 512; o > 0; o >>= 1) {
        if (tid < o) s[tid] += s[tid + o];
        __syncthreads();
    }
    if (tid == 0) {
        unsigned n = g_count;
        float denom = (n >= 1u) ? (float)n : 1.0f;
        dout[0] = s[0] / denom;
        dout[out_size - 1] = weight[0];
    }
}

// ============================================================================
extern "C" void kernel_launch(void* const* d_in, const int* in_sizes, int n_in,
                              void* d_out, int out_size) {
    const float* pos    = (const float*)d_in[0];
    // d_in[1] = adjacency: unused by the reference computation
    const int*   eidx   = (const int*)d_in[2];
    const float* weight = (const float*)d_in[3];
    int E = in_sizes[2] / 2;                    // 8192
    float* out = (float*)d_out;

    // zero-fill full output (mask + loss planes + scalars); pure DRAM stream
    cudaMemsetAsync(d_out, 0, (size_t)out_size * sizeof(float), 0);

    k_edges<<<(E + 255) / 256, 256>>>(pos, eidx, E);
    k_bsort<<<1, 256>>>(E);
    k_count<<<(E * 32 + 255) / 256, 256>>>(E);  // one warp per sorted pos
    k_scan<<<1, 1024>>>(E);
    k_emit<<<(E * 32 + 255) / 256, 256>>>(E);
    k_ranks<<<1, 256>>>();

    for (int p = 0; p < 4; p++) {
        k_hist<<<512, 256>>>(p);
        k_resolve<<<1, 256>>>(p);
    }

    int nsb = 1024;                             // scatter blocks (fits g_partial)
    k_scatter<<<nsb, 256>>>(out, E);
    k_reduce<<<1, 1024>>>(out, weight, (long long)out_size, nsb);
}